// round 12
// baseline (speedup 1.0000x reference)
#include <cuda_runtime.h>

// GaussianUpsampling: out[b,c,f] = sum_j softmax_j(-0.1*(f - c_j)^2) * x[b,c,j]
//   c = cumsum(w) - 0.5*w   (bit-matches JAX associative_scan Brent-Kung tree)
// B=16, C=256, T_text=512, T_feat=4096. Masks structurally all-true.
//
// R12: occupancy push. 64-channel CTAs (grid 128x4x16), 1ch x 8fr thread
// tile, __launch_bounds__(256,6) -> 48 warps/SM. x smem transposed [c][tok]
// with 16B-unit XOR swizzle: 1 LDS.128 per 4 tokens. cumsum = R11 register
// Brent-Kung (bit-exact).

#define NB 16
#define NC 256
#define NCH 64             // channels per CTA
#define TT 512
#define TFEAT 4096
#define DELTA_F 0.1f
#define TILE_F 32
#define NTILES (TFEAT / TILE_F)   // 128
#define MAXBAND 32
#define NTHREADS 256
#define FULLW 0xffffffffu

__device__ float g_c[NB * TT];
__device__ int2  g_band[NB * NTILES];

#define FMA2(acc, a, b) \
  asm("fma.rn.f32x2 %0, %1, %2, %0;" : "+l"(acc) : "l"(a), "l"(b))
#define MUL2(out, a, b) \
  asm("mul.rn.f32x2 %0, %1, %2;" : "=l"(out) : "l"(a), "l"(b))
#define PACK2(out, lo, hi) \
  asm("mov.b64 %0, {%1, %2};" : "=l"(out) : "f"(lo), "f"(hi))
#define UNPACK2(lo, hi, in) \
  asm("mov.b64 {%0, %1}, %2;" : "=f"(lo), "=f"(hi) : "l"(in))

__device__ __forceinline__ int lower_bound_s(const float* c, float v) {
  int lo = 0, hi = TT;
  while (lo < hi) { int m = (lo + hi) >> 1; if (c[m] < v) lo = m + 1; else hi = m; }
  return lo;
}

// ---------------------------------------------------------------------------
// Register Brent-Kung scan (warp 0) + parallel band computation (R11, kept).
// Tree identical to jax.lax.associative_scan's -> bit-exact c values.
// ---------------------------------------------------------------------------
__global__ void cumsum_kernel(const float* __restrict__ w) {
  __shared__ float c_sh[TT];
  const int b   = blockIdx.x;
  const int tid = threadIdx.x;

  if (tid < 32) {
    const int lane = tid;
    const float* wb = w + b * TT + 16 * lane;
    float b0[16];
    #pragma unroll
    for (int q = 0; q < 4; q++) {
      float4 t4 = *(const float4*)(wb + 4 * q);
      b0[4 * q] = t4.x; b0[4 * q + 1] = t4.y; b0[4 * q + 2] = t4.z; b0[4 * q + 3] = t4.w;
    }
    float b1[8], b2[4], b3[2], B4;
    #pragma unroll
    for (int j = 0; j < 8; j++) b1[j] = b0[2 * j] + b0[2 * j + 1];
    #pragma unroll
    for (int j = 0; j < 4; j++) b2[j] = b1[2 * j] + b1[2 * j + 1];
    #pragma unroll
    for (int j = 0; j < 2; j++) b3[j] = b2[2 * j] + b2[2 * j + 1];
    B4 = b3[0] + b3[1];
    float B5 = B4 + __shfl_down_sync(FULLW, B4, 1);
    float B6 = B5 + __shfl_down_sync(FULLW, B5, 2);
    float B7 = B6 + __shfl_down_sync(FULLW, B6, 4);
    float B8 = B7 + __shfl_down_sync(FULLW, B7, 8);
    float B9 = B8 + __shfl_down_sync(FULLW, B8, 16);
    float Sv = B9;
    #pragma unroll
    for (int lvl = 8; lvl >= 4; lvl--) {
      const int s = 1 << (lvl - 4);
      const float bl = (lvl == 8) ? B8 : (lvl == 7) ? B7 : (lvl == 6) ? B6
                     : (lvl == 5) ? B5 : B4;
      float up1 = __shfl_sync(FULLW, Sv, (lane >= s) ? lane - s : 0);
      float up2 = __shfl_sync(FULLW, Sv, (lane >= 2 * s) ? lane - 2 * s : 0);
      if ((lane & (s - 1)) == 0) {
        const int k = lane / s;
        Sv = (k == 0) ? bl : ((k & 1) ? up1 : up2 + bl);
      }
    }
    float P = __shfl_up_sync(FULLW, Sv, 1);
    const bool l0 = (lane == 0);
    float S3_0 = l0 ? b3[0] : P + b3[0];
    float S3_1 = Sv;
    float S2_0 = l0 ? b2[0] : P + b2[0];
    float S2_1 = S3_0;
    float S2_2 = S3_0 + b2[2];
    float S2_3 = S3_1;
    float S1[8];
    S1[0] = l0 ? b1[0] : P + b1[0];
    S1[1] = S2_0;
    S1[2] = S2_0 + b1[2];
    S1[3] = S2_1;
    S1[4] = S2_1 + b1[4];
    S1[5] = S2_2;
    S1[6] = S2_2 + b1[6];
    S1[7] = S2_3;
    float s[16];
    s[0] = l0 ? b0[0] : P + b0[0];
    #pragma unroll
    for (int m = 1; m < 16; m += 2) s[m] = S1[(m - 1) >> 1];
    #pragma unroll
    for (int m = 2; m < 16; m += 2) s[m] = S1[(m - 2) >> 1] + b0[m];
    float cv[16];
    #pragma unroll
    for (int m = 0; m < 16; m++) cv[m] = s[m] - 0.5f * b0[m];
    float* gc = g_c + b * TT + 16 * lane;
    #pragma unroll
    for (int q = 0; q < 4; q++) {
      float4 t4 = make_float4(cv[4 * q], cv[4 * q + 1], cv[4 * q + 2], cv[4 * q + 3]);
      *(float4*)(&c_sh[16 * lane + 4 * q]) = t4;
      *(float4*)(gc + 4 * q) = t4;
    }
  }
  __syncthreads();

  if (tid < NTILES) {
    const int t = tid;
    const float R = 18.0f;  // exp(-0.1*18^2) ~ 8e-15 relative
    float tmin = (float)(t * TILE_F);
    float tmax = tmin + (float)(TILE_F - 1);
    int jlo = lower_bound_s(c_sh, tmin - R);
    int jhi = lower_bound_s(c_sh, tmax + R);
    int plo = lower_bound_s(c_sh, tmin);
    int phi = lower_bound_s(c_sh, tmax);
    jlo = min(jlo, max(plo - 1, 0));
    jhi = max(jhi, min(phi + 1, TT));
    jlo &= ~3;
    if (jhi - jlo > MAXBAND) {
      int slack = (max(0, (plo - 1) - jlo)) & ~3;
      int need  = jhi - jlo - MAXBAND;
      int adv   = min((need + 3) & ~3, slack);
      jlo += adv;
      jhi = min(jhi, jlo + MAXBAND);
    }
    g_band[b * NTILES + t] = make_int2(jlo, jhi);
  }
}

// ---------------------------------------------------------------------------
// Fused banded softmax + GEMM. Block = (32-frame tile, channel quarter, b).
// 256 threads, thread tile 1ch x 8fr, target 42 regs -> 6 CTAs/SM.
// x_sT[c][tok]: 64 rows x 32 floats; 16B unit u stores tokens 4*(u^(c&7)).
// ---------------------------------------------------------------------------
__global__ __launch_bounds__(NTHREADS, 6) void gauss_kernel(
    const float* __restrict__ x, float* __restrict__ out)
{
  __shared__ __align__(16) float x_sT[NCH][TILE_F];       // 8 KB, swizzled
  __shared__ __align__(16) float attn_s[MAXBAND][TILE_F]; // unnormalized E
  __shared__ float c_sh[MAXBAND];
  __shared__ float ps[8][TILE_F];
  __shared__ __align__(16) float r_s[TILE_F];

  const int b    = blockIdx.z;
  const int quad = blockIdx.y;          // channel quarter 0..3
  const int f0   = blockIdx.x * TILE_F;
  const int tid  = threadIdx.x;

  const int2 bd = g_band[b * NTILES + blockIdx.x];
  const int jlo = bd.x;
  const int nband  = bd.y - jlo;
  const int nband4 = (nband + 3) & ~3;

  // ---- phase A: issue x loads (2 float4: 2 channels x 4 tokens) --------
  const int tq = tid & 7;            // token quad
  const int c0 = tid >> 3;           // channel 0..31 (and c0+32)
  const int row0 = 4 * tq;
  const bool doload = row0 < nband4;
  float4 v[2];
  if (doload) {
    const bool full = (row0 + 4 <= nband);
    const float* xb = x + ((size_t)b * NC + quad * NCH) * TT + jlo + row0;
    #pragma unroll
    for (int p = 0; p < 2; p++) {
      const float* src = xb + (size_t)(c0 + 32 * p) * TT;
      if (full) {
        v[p] = *(const float4*)src;
      } else {
        v[p].x = (row0     < nband) ? src[0] : 0.0f;
        v[p].y = (row0 + 1 < nband) ? src[1] : 0.0f;
        v[p].z = (row0 + 2 < nband) ? src[2] : 0.0f;
        v[p].w = (row0 + 3 < nband) ? src[3] : 0.0f;
      }
    }
  }

  if (tid < MAXBAND)
    c_sh[tid] = (tid < nband) ? g_c[b * TT + jlo + tid] : 3.0e38f;
  __syncthreads();                                   // #1: c_sh ready

  // ---- phase B: analytic softmax max + exp + partial sums; x STS -------
  const int fE   = tid & 31;         // frame within tile
  const int kgrp = tid >> 5;         // 0..7
  {
    const float tf = (float)(f0 + fE);
    int lo = 0, hi = nband;          // nearest center (<=5 steps)
    while (lo < hi) { int mid = (lo + hi) >> 1; if (c_sh[mid] < tf) lo = mid + 1; else hi = mid; }
    float dR = (lo < nband) ? (c_sh[lo] - tf) : 3.0e38f;
    float dL = (lo > 0)     ? (tf - c_sh[lo - 1]) : 3.0e38f;
    float dmin = fminf(dL, dR);
    const float m = -DELTA_F * (dmin * dmin);        // exact band max

    float sloc = 0.0f;
    #pragma unroll
    for (int u = 0; u < 4; u++) {
      const int kk = kgrp + 8 * u;
      float E = 0.0f;
      if (kk < nband) {
        float d = tf - c_sh[kk];
        E = __expf(-DELTA_F * (d * d) - m);          // <= 1, NaN-safe
      }
      attn_s[kk][fE] = E;
      sloc += E;
    }
    ps[kgrp][fE] = sloc;
  }
  if (doload) {
    #pragma unroll
    for (int p = 0; p < 2; p++) {
      const int c = c0 + 32 * p;
      const int u = tq ^ (c & 7);                    // 16B-unit swizzle
      *(float4*)&x_sT[c][4 * u] = v[p];
    }
  }
  __syncthreads();                                   // #2: attn_s, x_sT, ps ready
  if (tid < TILE_F) {
    float s = ps[0][tid];
    #pragma unroll
    for (int k = 1; k < 8; k++) s += ps[k][tid];
    r_s[tid] = 1.0f / s;
  }

  // ---- main FMA loop: per 4 tokens: 1 LDS.128 x + 8 LDS.128 attn -------
  const int ch = tid >> 2;            // 0..63: this thread's channel
  const int fg = (tid & 3) << 3;      // frame base (8 frames)
  const float* xr = &x_sT[ch][0];

  unsigned long long acc2[4];
  #pragma unroll
  for (int q = 0; q < 4; q++) acc2[q] = 0ull;

  for (int kk0 = 0; kk0 < nband4; kk0 += 4) {
    const int pu = (kk0 >> 2) ^ (ch & 7);
    float4 xq = *(const float4*)&xr[4 * pu];         // tokens kk0..kk0+3
    float xv[4] = {xq.x, xq.y, xq.z, xq.w};
    #pragma unroll
    for (int u = 0; u < 4; u++) {
      const int kk = kk0 + u;
      ulonglong2 a01 = *(const ulonglong2*)&attn_s[kk][fg];
      ulonglong2 a23 = *(const ulonglong2*)&attn_s[kk][fg + 4];
      unsigned long long xp;
      PACK2(xp, xv[u], xv[u]);
      FMA2(acc2[0], xp, a01.x);
      FMA2(acc2[1], xp, a01.y);
      FMA2(acc2[2], xp, a23.x);
      FMA2(acc2[3], xp, a23.y);
    }
  }
  __syncthreads();                                   // #3: r_s ready

  // ---- epilogue: normalize by r[f], store ------------------------------
  ulonglong2 r01 = *(const ulonglong2*)&r_s[fg];
  ulonglong2 r23 = *(const ulonglong2*)&r_s[fg + 4];
  unsigned long long rp[4] = {r01.x, r01.y, r23.x, r23.y};

  float r[8];
  #pragma unroll
  for (int q = 0; q < 4; q++) {
    unsigned long long t;
    MUL2(t, acc2[q], rp[q]);
    UNPACK2(r[2 * q], r[2 * q + 1], t);
  }
  float* o = out + ((size_t)b * NC + quad * NCH + ch) * TFEAT + f0 + fg;
  *(float4*)&o[0] = make_float4(r[0], r[1], r[2], r[3]);
  *(float4*)&o[4] = make_float4(r[4], r[5], r[6], r[7]);
}

extern "C" void kernel_launch(void* const* d_in, const int* in_sizes, int n_in,
                              void* d_out, int out_size) {
  const float* x = (const float*)d_in[0];   // (B, C, T_text) fp32
  const float* w = (const float*)d_in[1];   // (B, T_text)    fp32
  float* out = (float*)d_out;               // (B, C, T_feat) fp32

  cumsum_kernel<<<NB, NTHREADS>>>(w);
  gauss_kernel<<<dim3(NTILES, 4, NB), NTHREADS>>>(x, out);
}

// round 13
// speedup vs baseline: 1.2751x; 1.2751x over previous
#include <cuda_runtime.h>

// GaussianUpsampling: out[b,c,f] = sum_j softmax_j(-0.1*(f - c_j)^2) * x[b,c,j]
//   c = cumsum(w) - 0.5*w   (bit-matches JAX associative_scan Brent-Kung tree)
// B=16, C=256, T_text=512, T_feat=4096. Masks structurally all-true.
//
// R13: L1-bandwidth-driven shape. One CTA = 256ch x 32fr (grid 128x16),
// thread tile 4ch x 8fr at <=64 regs (4 CTAs/SM): attn smem bytes amortized
// over 4 channels -> 3 B/FMA (was 5). exp computed once per full channel set.
// cumsum = R11 register Brent-Kung (bit-exact).

#define NB 16
#define NC 256
#define TT 512
#define TFEAT 4096
#define DELTA_F 0.1f
#define TILE_F 32
#define NTILES (TFEAT / TILE_F)   // 128
#define MAXBAND 32
#define NTHREADS 256
#define FULLW 0xffffffffu

__device__ float g_c[NB * TT];
__device__ int2  g_band[NB * NTILES];

#define FMA2(acc, a, b) \
  asm("fma.rn.f32x2 %0, %1, %2, %0;" : "+l"(acc) : "l"(a), "l"(b))
#define MUL2(out, a, b) \
  asm("mul.rn.f32x2 %0, %1, %2;" : "=l"(out) : "l"(a), "l"(b))
#define PACK2(out, lo, hi) \
  asm("mov.b64 %0, {%1, %2};" : "=l"(out) : "f"(lo), "f"(hi))
#define UNPACK2(lo, hi, in) \
  asm("mov.b64 {%0, %1}, %2;" : "=f"(lo), "=f"(hi) : "l"(in))

__device__ __forceinline__ int lower_bound_s(const float* c, float v) {
  int lo = 0, hi = TT;
  while (lo < hi) { int m = (lo + hi) >> 1; if (c[m] < v) lo = m + 1; else hi = m; }
  return lo;
}

// ---------------------------------------------------------------------------
// Register Brent-Kung scan (warp 0) + parallel band computation (R11, kept).
// ---------------------------------------------------------------------------
__global__ void cumsum_kernel(const float* __restrict__ w) {
  __shared__ float c_sh[TT];
  const int b   = blockIdx.x;
  const int tid = threadIdx.x;

  if (tid < 32) {
    const int lane = tid;
    const float* wb = w + b * TT + 16 * lane;
    float b0[16];
    #pragma unroll
    for (int q = 0; q < 4; q++) {
      float4 t4 = *(const float4*)(wb + 4 * q);
      b0[4 * q] = t4.x; b0[4 * q + 1] = t4.y; b0[4 * q + 2] = t4.z; b0[4 * q + 3] = t4.w;
    }
    float b1[8], b2[4], b3[2], B4;
    #pragma unroll
    for (int j = 0; j < 8; j++) b1[j] = b0[2 * j] + b0[2 * j + 1];
    #pragma unroll
    for (int j = 0; j < 4; j++) b2[j] = b1[2 * j] + b1[2 * j + 1];
    #pragma unroll
    for (int j = 0; j < 2; j++) b3[j] = b2[2 * j] + b2[2 * j + 1];
    B4 = b3[0] + b3[1];
    float B5 = B4 + __shfl_down_sync(FULLW, B4, 1);
    float B6 = B5 + __shfl_down_sync(FULLW, B5, 2);
    float B7 = B6 + __shfl_down_sync(FULLW, B6, 4);
    float B8 = B7 + __shfl_down_sync(FULLW, B7, 8);
    float B9 = B8 + __shfl_down_sync(FULLW, B8, 16);
    float Sv = B9;
    #pragma unroll
    for (int lvl = 8; lvl >= 4; lvl--) {
      const int s = 1 << (lvl - 4);
      const float bl = (lvl == 8) ? B8 : (lvl == 7) ? B7 : (lvl == 6) ? B6
                     : (lvl == 5) ? B5 : B4;
      float up1 = __shfl_sync(FULLW, Sv, (lane >= s) ? lane - s : 0);
      float up2 = __shfl_sync(FULLW, Sv, (lane >= 2 * s) ? lane - 2 * s : 0);
      if ((lane & (s - 1)) == 0) {
        const int k = lane / s;
        Sv = (k == 0) ? bl : ((k & 1) ? up1 : up2 + bl);
      }
    }
    float P = __shfl_up_sync(FULLW, Sv, 1);
    const bool l0 = (lane == 0);
    float S3_0 = l0 ? b3[0] : P + b3[0];
    float S3_1 = Sv;
    float S2_0 = l0 ? b2[0] : P + b2[0];
    float S2_1 = S3_0;
    float S2_2 = S3_0 + b2[2];
    float S2_3 = S3_1;
    float S1[8];
    S1[0] = l0 ? b1[0] : P + b1[0];
    S1[1] = S2_0;
    S1[2] = S2_0 + b1[2];
    S1[3] = S2_1;
    S1[4] = S2_1 + b1[4];
    S1[5] = S2_2;
    S1[6] = S2_2 + b1[6];
    S1[7] = S2_3;
    float s[16];
    s[0] = l0 ? b0[0] : P + b0[0];
    #pragma unroll
    for (int m = 1; m < 16; m += 2) s[m] = S1[(m - 1) >> 1];
    #pragma unroll
    for (int m = 2; m < 16; m += 2) s[m] = S1[(m - 2) >> 1] + b0[m];
    float cv[16];
    #pragma unroll
    for (int m = 0; m < 16; m++) cv[m] = s[m] - 0.5f * b0[m];
    float* gc = g_c + b * TT + 16 * lane;
    #pragma unroll
    for (int q = 0; q < 4; q++) {
      float4 t4 = make_float4(cv[4 * q], cv[4 * q + 1], cv[4 * q + 2], cv[4 * q + 3]);
      *(float4*)(&c_sh[16 * lane + 4 * q]) = t4;
      *(float4*)(gc + 4 * q) = t4;
    }
  }
  __syncthreads();

  if (tid < NTILES) {
    const int t = tid;
    const float R = 18.0f;  // exp(-0.1*18^2) ~ 8e-15 relative
    float tmin = (float)(t * TILE_F);
    float tmax = tmin + (float)(TILE_F - 1);
    int jlo = lower_bound_s(c_sh, tmin - R);
    int jhi = lower_bound_s(c_sh, tmax + R);
    int plo = lower_bound_s(c_sh, tmin);
    int phi = lower_bound_s(c_sh, tmax);
    jlo = min(jlo, max(plo - 1, 0));
    jhi = max(jhi, min(phi + 1, TT));
    jlo &= ~3;
    if (jhi - jlo > MAXBAND) {
      int slack = (max(0, (plo - 1) - jlo)) & ~3;
      int need  = jhi - jlo - MAXBAND;
      int adv   = min((need + 3) & ~3, slack);
      jlo += adv;
      jhi = min(jhi, jlo + MAXBAND);
    }
    g_band[b * NTILES + t] = make_int2(jlo, jhi);
  }
}

// ---------------------------------------------------------------------------
// Fused banded softmax + GEMM. Block = (32-frame tile, batch), 256 threads,
// full 256 channels. Thread tile 4ch x 8fr; target 64 regs -> 4 CTAs/SM.
// x_s[tok][256ch] token-major, R5 XOR swizzle (col = 4*((c>>2)^tq)+(c&3)).
// ---------------------------------------------------------------------------
__global__ __launch_bounds__(NTHREADS, 4) void gauss_kernel(
    const float* __restrict__ x, float* __restrict__ out)
{
  __shared__ __align__(16) float x_s[MAXBAND][NC];        // 32 KB, swizzled
  __shared__ __align__(16) float attn_s[MAXBAND][TILE_F]; // unnormalized E
  __shared__ float c_sh[MAXBAND];
  __shared__ float ps[8][TILE_F];
  __shared__ __align__(16) float r_s[TILE_F];

  const int b   = blockIdx.y;
  const int f0  = blockIdx.x * TILE_F;
  const int tid = threadIdx.x;

  const int2 bd = g_band[b * NTILES + blockIdx.x];
  const int jlo = bd.x;
  const int nband  = bd.y - jlo;
  const int nband4 = (nband + 3) & ~3;

  // ---- phase A: issue x loads (8 float4: 8 channels x 4 tokens) --------
  const int cl  = tid & 3;
  const int tq  = (tid >> 2) & 7;
  const int rep = tid >> 5;          // 0..7
  const int row0 = 4 * tq;
  const bool doload = row0 < nband4;
  float4 v[8];
  if (doload) {
    const bool full = (row0 + 4 <= nband);
    const float* xb = x + (size_t)b * NC * TT + jlo + row0;
    #pragma unroll
    for (int p = 0; p < 8; p++) {
      const int c = cl + 4 * rep + 32 * p;
      const float* src = xb + (size_t)c * TT;
      if (full) {
        v[p] = *(const float4*)src;
      } else {
        v[p].x = (row0     < nband) ? src[0] : 0.0f;
        v[p].y = (row0 + 1 < nband) ? src[1] : 0.0f;
        v[p].z = (row0 + 2 < nband) ? src[2] : 0.0f;
        v[p].w = (row0 + 3 < nband) ? src[3] : 0.0f;
      }
    }
  }

  if (tid < MAXBAND)
    c_sh[tid] = (tid < nband) ? g_c[b * TT + jlo + tid] : 3.0e38f;
  __syncthreads();                                   // #1: c_sh ready

  // ---- phase B: analytic softmax max + exp + partial sums; x STS -------
  const int fE   = tid & 31;         // frame within tile
  const int kgrp = tid >> 5;         // 0..7
  {
    const float tf = (float)(f0 + fE);
    int lo = 0, hi = nband;          // nearest center (<=5 steps)
    while (lo < hi) { int mid = (lo + hi) >> 1; if (c_sh[mid] < tf) lo = mid + 1; else hi = mid; }
    float dR = (lo < nband) ? (c_sh[lo] - tf) : 3.0e38f;
    float dL = (lo > 0)     ? (tf - c_sh[lo - 1]) : 3.0e38f;
    float dmin = fminf(dL, dR);
    const float m = -DELTA_F * (dmin * dmin);        // exact band max

    float sloc = 0.0f;
    #pragma unroll
    for (int u = 0; u < 4; u++) {
      const int kk = kgrp + 8 * u;
      float E = 0.0f;
      if (kk < nband) {
        float d = tf - c_sh[kk];
        E = __expf(-DELTA_F * (d * d) - m);          // <= 1, NaN-safe
      }
      attn_s[kk][fE] = E;
      sloc += E;
    }
    ps[kgrp][fE] = sloc;
  }
  if (doload) {
    #pragma unroll
    for (int p = 0; p < 8; p++) {
      const int cq  = rep + 8 * p;                   // = c>>2
      const int col = 4 * (cq ^ tq) + cl;            // XOR swizzle: conflict-free
      x_s[row0 + 0][col] = v[p].x;
      x_s[row0 + 1][col] = v[p].y;
      x_s[row0 + 2][col] = v[p].z;
      x_s[row0 + 3][col] = v[p].w;
    }
  }
  __syncthreads();                                   // #2: attn_s, x_s, ps ready
  if (tid < TILE_F) {
    float s = ps[0][tid];
    #pragma unroll
    for (int k = 1; k < 8; k++) s += ps[k][tid];
    r_s[tid] = 1.0f / s;
  }

  // ---- main FMA loop: 4ch x 8fr; per 4 tokens: 9 LDS.128, 64 FFMA2 -----
  const int cgrp = tid >> 2;          // 0..63: channels 4*cgrp..4*cgrp+3
  const int fg   = (tid & 3) << 3;    // frame base (8 frames)

  unsigned long long acc2[4][4];      // [channel][frame-pair]
  #pragma unroll
  for (int ci = 0; ci < 4; ci++)
    #pragma unroll
    for (int q = 0; q < 4; q++) acc2[ci][q] = 0ull;

  for (int kk0 = 0; kk0 < nband4; kk0 += 4) {
    const int colb = 4 * (cgrp ^ (kk0 >> 2));        // physical unit of our 4ch
    float4 xq[4];                                    // xq[u] loaded per token below
    #pragma unroll
    for (int u = 0; u < 4; u++)
      xq[u] = *(const float4*)&x_s[kk0 + u][colb];   // 4 channels, token kk0+u
    #pragma unroll
    for (int u = 0; u < 4; u++) {
      const int kk = kk0 + u;
      ulonglong2 a01 = *(const ulonglong2*)&attn_s[kk][fg];
      ulonglong2 a23 = *(const ulonglong2*)&attn_s[kk][fg + 4];
      float xc[4] = {xq[u].x, xq[u].y, xq[u].z, xq[u].w};
      #pragma unroll
      for (int ci = 0; ci < 4; ci++) {
        unsigned long long xp;
        PACK2(xp, xc[ci], xc[ci]);
        FMA2(acc2[ci][0], xp, a01.x);
        FMA2(acc2[ci][1], xp, a01.y);
        FMA2(acc2[ci][2], xp, a23.x);
        FMA2(acc2[ci][3], xp, a23.y);
      }
    }
  }
  __syncthreads();                                   // #3: r_s ready

  // ---- epilogue: normalize by r[f], store ------------------------------
  ulonglong2 r01 = *(const ulonglong2*)&r_s[fg];
  ulonglong2 r23 = *(const ulonglong2*)&r_s[fg + 4];
  unsigned long long rp[4] = {r01.x, r01.y, r23.x, r23.y};

  #pragma unroll
  for (int ci = 0; ci < 4; ci++) {
    float r[8];
    #pragma unroll
    for (int q = 0; q < 4; q++) {
      unsigned long long t;
      MUL2(t, acc2[ci][q], rp[q]);
      UNPACK2(r[2 * q], r[2 * q + 1], t);
    }
    float* o = out + ((size_t)b * NC + 4 * cgrp + ci) * TFEAT + f0 + fg;
    *(float4*)&o[0] = make_float4(r[0], r[1], r[2], r[3]);
    *(float4*)&o[4] = make_float4(r[4], r[5], r[6], r[7]);
  }
}

extern "C" void kernel_launch(void* const* d_in, const int* in_sizes, int n_in,
                              void* d_out, int out_size) {
  const float* x = (const float*)d_in[0];   // (B, C, T_text) fp32
  const float* w = (const float*)d_in[1];   // (B, T_text)    fp32
  float* out = (float*)d_out;               // (B, C, T_feat) fp32

  cumsum_kernel<<<NB, NTHREADS>>>(w);
  gauss_kernel<<<dim3(NTILES, NB), NTHREADS>>>(x, out);
}

// round 14
// speedup vs baseline: 1.3478x; 1.0571x over previous
#include <cuda_runtime.h>

// GaussianUpsampling: out[b,c,f] = sum_j softmax_j(-0.1*(f - c_j)^2) * x[b,c,j]
//   c = cumsum(w) - 0.5*w   (bit-matches JAX associative_scan Brent-Kung tree)
// B=16, C=256, T_text=512, T_feat=4096. Masks structurally all-true.
//
// R14: wavefront-minimal mappings. Thread tile 8ch x 4fr -> STG at the
// 128B-line floor (4 rows/warp, full lines), attn 1 LDS.128/token. x smem
// transposed [c][tok] (token-quad units, per-row XOR key (c>>2)&7): STS.128
// conflict-free, main-loop x reads broadcast. cumsum = R11 (bit-exact).

#define NB 16
#define NC 256
#define TT 512
#define TFEAT 4096
#define DELTA_F 0.1f
#define TILE_F 32
#define NTILES (TFEAT / TILE_F)   // 128
#define MAXBAND 32
#define NTHREADS 256
#define FULLW 0xffffffffu

__device__ float g_c[NB * TT];
__device__ int2  g_band[NB * NTILES];

#define FMA2(acc, a, b) \
  asm("fma.rn.f32x2 %0, %1, %2, %0;" : "+l"(acc) : "l"(a), "l"(b))
#define MUL2(out, a, b) \
  asm("mul.rn.f32x2 %0, %1, %2;" : "=l"(out) : "l"(a), "l"(b))
#define PACK2(out, lo, hi) \
  asm("mov.b64 %0, {%1, %2};" : "=l"(out) : "f"(lo), "f"(hi))
#define UNPACK2(lo, hi, in) \
  asm("mov.b64 {%0, %1}, %2;" : "=f"(lo), "=f"(hi) : "l"(in))

__device__ __forceinline__ int lower_bound_s(const float* c, float v) {
  int lo = 0, hi = TT;
  while (lo < hi) { int m = (lo + hi) >> 1; if (c[m] < v) lo = m + 1; else hi = m; }
  return lo;
}

// ---------------------------------------------------------------------------
// Register Brent-Kung scan (warp 0) + parallel band computation (R11, kept).
// ---------------------------------------------------------------------------
__global__ void cumsum_kernel(const float* __restrict__ w) {
  __shared__ float c_sh[TT];
  const int b   = blockIdx.x;
  const int tid = threadIdx.x;

  if (tid < 32) {
    const int lane = tid;
    const float* wb = w + b * TT + 16 * lane;
    float b0[16];
    #pragma unroll
    for (int q = 0; q < 4; q++) {
      float4 t4 = *(const float4*)(wb + 4 * q);
      b0[4 * q] = t4.x; b0[4 * q + 1] = t4.y; b0[4 * q + 2] = t4.z; b0[4 * q + 3] = t4.w;
    }
    float b1[8], b2[4], b3[2], B4;
    #pragma unroll
    for (int j = 0; j < 8; j++) b1[j] = b0[2 * j] + b0[2 * j + 1];
    #pragma unroll
    for (int j = 0; j < 4; j++) b2[j] = b1[2 * j] + b1[2 * j + 1];
    #pragma unroll
    for (int j = 0; j < 2; j++) b3[j] = b2[2 * j] + b2[2 * j + 1];
    B4 = b3[0] + b3[1];
    float B5 = B4 + __shfl_down_sync(FULLW, B4, 1);
    float B6 = B5 + __shfl_down_sync(FULLW, B5, 2);
    float B7 = B6 + __shfl_down_sync(FULLW, B6, 4);
    float B8 = B7 + __shfl_down_sync(FULLW, B7, 8);
    float B9 = B8 + __shfl_down_sync(FULLW, B8, 16);
    float Sv = B9;
    #pragma unroll
    for (int lvl = 8; lvl >= 4; lvl--) {
      const int s = 1 << (lvl - 4);
      const float bl = (lvl == 8) ? B8 : (lvl == 7) ? B7 : (lvl == 6) ? B6
                     : (lvl == 5) ? B5 : B4;
      float up1 = __shfl_sync(FULLW, Sv, (lane >= s) ? lane - s : 0);
      float up2 = __shfl_sync(FULLW, Sv, (lane >= 2 * s) ? lane - 2 * s : 0);
      if ((lane & (s - 1)) == 0) {
        const int k = lane / s;
        Sv = (k == 0) ? bl : ((k & 1) ? up1 : up2 + bl);
      }
    }
    float P = __shfl_up_sync(FULLW, Sv, 1);
    const bool l0 = (lane == 0);
    float S3_0 = l0 ? b3[0] : P + b3[0];
    float S3_1 = Sv;
    float S2_0 = l0 ? b2[0] : P + b2[0];
    float S2_1 = S3_0;
    float S2_2 = S3_0 + b2[2];
    float S2_3 = S3_1;
    float S1[8];
    S1[0] = l0 ? b1[0] : P + b1[0];
    S1[1] = S2_0;
    S1[2] = S2_0 + b1[2];
    S1[3] = S2_1;
    S1[4] = S2_1 + b1[4];
    S1[5] = S2_2;
    S1[6] = S2_2 + b1[6];
    S1[7] = S2_3;
    float s[16];
    s[0] = l0 ? b0[0] : P + b0[0];
    #pragma unroll
    for (int m = 1; m < 16; m += 2) s[m] = S1[(m - 1) >> 1];
    #pragma unroll
    for (int m = 2; m < 16; m += 2) s[m] = S1[(m - 2) >> 1] + b0[m];
    float cv[16];
    #pragma unroll
    for (int m = 0; m < 16; m++) cv[m] = s[m] - 0.5f * b0[m];
    float* gc = g_c + b * TT + 16 * lane;
    #pragma unroll
    for (int q = 0; q < 4; q++) {
      float4 t4 = make_float4(cv[4 * q], cv[4 * q + 1], cv[4 * q + 2], cv[4 * q + 3]);
      *(float4*)(&c_sh[16 * lane + 4 * q]) = t4;
      *(float4*)(gc + 4 * q) = t4;
    }
  }
  __syncthreads();

  if (tid < NTILES) {
    const int t = tid;
    const float R = 18.0f;  // exp(-0.1*18^2) ~ 8e-15 relative
    float tmin = (float)(t * TILE_F);
    float tmax = tmin + (float)(TILE_F - 1);
    int jlo = lower_bound_s(c_sh, tmin - R);
    int jhi = lower_bound_s(c_sh, tmax + R);
    int plo = lower_bound_s(c_sh, tmin);
    int phi = lower_bound_s(c_sh, tmax);
    jlo = min(jlo, max(plo - 1, 0));
    jhi = max(jhi, min(phi + 1, TT));
    jlo &= ~3;
    if (jhi - jlo > MAXBAND) {
      int slack = (max(0, (plo - 1) - jlo)) & ~3;
      int need  = jhi - jlo - MAXBAND;
      int adv   = min((need + 3) & ~3, slack);
      jlo += adv;
      jhi = min(jhi, jlo + MAXBAND);
    }
    g_band[b * NTILES + t] = make_int2(jlo, jhi);
  }
}

// ---------------------------------------------------------------------------
// Fused banded softmax + GEMM. Block = (32-frame tile, batch), 256 threads,
// full 256 channels. Thread tile 8ch x 4fr; target <=64 regs, 4 CTAs/SM.
// x_sT[c][tok]: row c = 32 tokens (128B); 16B unit u holds tokens 4u', with
// physical u = u' ^ ((c>>2)&7).
// ---------------------------------------------------------------------------
__global__ __launch_bounds__(NTHREADS, 4) void gauss_kernel(
    const float* __restrict__ x, float* __restrict__ out)
{
  __shared__ __align__(16) float x_sT[NC][MAXBAND];       // 32 KB, swizzled
  __shared__ __align__(16) float attn_s[MAXBAND][TILE_F]; // unnormalized E
  __shared__ float c_sh[MAXBAND];
  __shared__ float ps[8][TILE_F];
  __shared__ __align__(16) float r_s[TILE_F];

  const int b   = blockIdx.y;
  const int f0  = blockIdx.x * TILE_F;
  const int tid = threadIdx.x;

  const int2 bd = g_band[b * NTILES + blockIdx.x];
  const int jlo = bd.x;
  const int nband  = bd.y - jlo;
  const int nband4 = (nband + 3) & ~3;

  // ---- phase A: issue x loads (8 float4: 8 channels x 4 tokens) --------
  // lanes: tq = tid&7 (token quad), cl = (tid>>3)&3, rep = warp id.
  const int tq  = tid & 7;
  const int cl  = (tid >> 3) & 3;
  const int rep = tid >> 5;          // 0..7
  const int row0 = 4 * tq;
  const bool doload = row0 < nband4;
  float4 v[8];
  if (doload) {
    const bool full = (row0 + 4 <= nband);
    const float* xb = x + (size_t)b * NC * TT + jlo + row0;
    #pragma unroll
    for (int p = 0; p < 8; p++) {
      const int c = cl + 4 * rep + 32 * p;
      const float* src = xb + (size_t)c * TT;
      if (full) {
        v[p] = *(const float4*)src;
      } else {
        v[p].x = (row0     < nband) ? src[0] : 0.0f;
        v[p].y = (row0 + 1 < nband) ? src[1] : 0.0f;
        v[p].z = (row0 + 2 < nband) ? src[2] : 0.0f;
        v[p].w = (row0 + 3 < nband) ? src[3] : 0.0f;
      }
    }
  }

  if (tid < MAXBAND)
    c_sh[tid] = (tid < nband) ? g_c[b * TT + jlo + tid] : 3.0e38f;
  __syncthreads();                                   // #1: c_sh ready

  // ---- phase B: analytic softmax max + exp + partial sums; x STS -------
  const int fE   = tid & 31;         // frame within tile
  const int kgrp = tid >> 5;         // 0..7
  {
    const float tf = (float)(f0 + fE);
    int lo = 0, hi = nband;          // nearest center (<=5 steps)
    while (lo < hi) { int mid = (lo + hi) >> 1; if (c_sh[mid] < tf) lo = mid + 1; else hi = mid; }
    float dR = (lo < nband) ? (c_sh[lo] - tf) : 3.0e38f;
    float dL = (lo > 0)     ? (tf - c_sh[lo - 1]) : 3.0e38f;
    float dmin = fminf(dL, dR);
    const float m = -DELTA_F * (dmin * dmin);        // exact band max

    float sloc = 0.0f;
    #pragma unroll
    for (int u = 0; u < 4; u++) {
      const int kk = kgrp + 8 * u;
      float E = 0.0f;
      if (kk < nband) {
        float d = tf - c_sh[kk];
        E = __expf(-DELTA_F * (d * d) - m);          // <= 1, NaN-safe
      }
      attn_s[kk][fE] = E;
      sloc += E;
    }
    ps[kgrp][fE] = sloc;
  }
  if (doload) {
    // STS.128: row c, unit u = tq ^ ((c>>2)&7) = tq ^ rep. Subphase lanes
    // share cl (same row), tq spans 8 -> full 128B row per phase.
    #pragma unroll
    for (int p = 0; p < 8; p++) {
      const int c = cl + 4 * rep + 32 * p;
      const int u = tq ^ rep;
      *(float4*)&x_sT[c][4 * u] = v[p];
    }
  }
  __syncthreads();                                   // #2: attn_s, x_sT, ps ready
  if (tid < TILE_F) {
    float s = ps[0][tid];
    #pragma unroll
    for (int k = 1; k < 8; k++) s += ps[k][tid];
    r_s[tid] = 1.0f / s;
  }

  // ---- main FMA loop: 8ch x 4fr ---------------------------------------
  const int cg8 = tid >> 3;           // 0..31: channels 8*cg8 .. 8*cg8+7
  const int fg  = (tid & 7) << 2;     // frame base (4 frames)

  unsigned long long acc2[8][2];      // [channel][frame-pair]
  #pragma unroll
  for (int ci = 0; ci < 8; ci++) { acc2[ci][0] = 0ull; acc2[ci][1] = 0ull; }

  for (int kk0 = 0; kk0 < nband4; kk0 += 4) {
    #pragma unroll
    for (int h = 0; h < 2; h++) {                    // channel halves: regs <= 64
      const int key = (2 * cg8 + h) & 7;
      const int u4  = ((kk0 >> 2) ^ key) << 2;
      float4 xq[4];                                  // 4 channels x 4 tokens
      #pragma unroll
      for (int ci = 0; ci < 4; ci++)
        xq[ci] = *(const float4*)&x_sT[8 * cg8 + 4 * h + ci][u4];
      #pragma unroll
      for (int u = 0; u < 4; u++) {
        ulonglong2 ap = *(const ulonglong2*)&attn_s[kk0 + u][fg];
        const float xc[4] = {
          (u == 0) ? xq[0].x : (u == 1) ? xq[0].y : (u == 2) ? xq[0].z : xq[0].w,
          (u == 0) ? xq[1].x : (u == 1) ? xq[1].y : (u == 2) ? xq[1].z : xq[1].w,
          (u == 0) ? xq[2].x : (u == 1) ? xq[2].y : (u == 2) ? xq[2].z : xq[2].w,
          (u == 0) ? xq[3].x : (u == 1) ? xq[3].y : (u == 2) ? xq[3].z : xq[3].w };
        #pragma unroll
        for (int ci = 0; ci < 4; ci++) {
          unsigned long long xp;
          PACK2(xp, xc[ci], xc[ci]);
          FMA2(acc2[4 * h + ci][0], xp, ap.x);
          FMA2(acc2[4 * h + ci][1], xp, ap.y);
        }
      }
    }
  }
  __syncthreads();                                   // #3: r_s ready

  // ---- epilogue: normalize by r[f], store (4 rows/warp, full lines) ----
  ulonglong2 rp = *(const ulonglong2*)&r_s[fg];      // (r0,r1),(r2,r3)

  #pragma unroll
  for (int ci = 0; ci < 8; ci++) {
    unsigned long long t0, t1;
    MUL2(t0, acc2[ci][0], rp.x);
    MUL2(t1, acc2[ci][1], rp.y);
    float r0, r1, r2, r3;
    UNPACK2(r0, r1, t0);
    UNPACK2(r2, r3, t1);
    float* o = out + ((size_t)b * NC + 8 * cg8 + ci) * TFEAT + f0 + fg;
    *(float4*)o = make_float4(r0, r1, r2, r3);
  }
}

extern "C" void kernel_launch(void* const* d_in, const int* in_sizes, int n_in,
                              void* d_out, int out_size) {
  const float* x = (const float*)d_in[0];   // (B, C, T_text) fp32
  const float* w = (const float*)d_in[1];   // (B, T_text)    fp32
  float* out = (float*)d_out;               // (B, C, T_feat) fp32

  cumsum_kernel<<<NB, NTHREADS>>>(w);
  gauss_kernel<<<dim3(NTILES, NB), NTHREADS>>>(x, out);
}

// round 15
// speedup vs baseline: 1.3503x; 1.0018x over previous
#include <cuda_runtime.h>

// GaussianUpsampling: out[b,c,f] = sum_j softmax_j(-0.1*(f - c_j)^2) * x[b,c,j]
//   c = cumsum(w) - 0.5*w   (bit-matches JAX associative_scan Brent-Kung tree)
// B=16, C=256, T_text=512, T_feat=4096. Masks structurally all-true.
//
// R15: R14 structure (8ch x 4fr, transposed swizzled x smem, analytic max)
// + tightened band radius R=14 (omitted mass <= ~2e-6 relative) and PDL
// overlap between cumsum and gauss (griddepcontrol).

#define NB 16
#define NC 256
#define TT 512
#define TFEAT 4096
#define DELTA_F 0.1f
#define TILE_F 32
#define NTILES (TFEAT / TILE_F)   // 128
#define MAXBAND 32
#define NTHREADS 256
#define FULLW 0xffffffffu

__device__ float g_c[NB * TT];
__device__ int2  g_band[NB * NTILES];

#define FMA2(acc, a, b) \
  asm("fma.rn.f32x2 %0, %1, %2, %0;" : "+l"(acc) : "l"(a), "l"(b))
#define MUL2(out, a, b) \
  asm("mul.rn.f32x2 %0, %1, %2;" : "=l"(out) : "l"(a), "l"(b))
#define PACK2(out, lo, hi) \
  asm("mov.b64 %0, {%1, %2};" : "=l"(out) : "f"(lo), "f"(hi))
#define UNPACK2(lo, hi, in) \
  asm("mov.b64 {%0, %1}, %2;" : "=f"(lo), "=f"(hi) : "l"(in))

__device__ __forceinline__ int lower_bound_s(const float* c, float v) {
  int lo = 0, hi = TT;
  while (lo < hi) { int m = (lo + hi) >> 1; if (c[m] < v) lo = m + 1; else hi = m; }
  return lo;
}

// ---------------------------------------------------------------------------
// Register Brent-Kung scan (warp 0) + parallel band computation.
// Tree identical to jax.lax.associative_scan's -> bit-exact c values.
// ---------------------------------------------------------------------------
__global__ void cumsum_kernel(const float* __restrict__ w) {
  __shared__ float c_sh[TT];
  const int b   = blockIdx.x;
  const int tid = threadIdx.x;

  if (tid < 32) {
    const int lane = tid;
    const float* wb = w + b * TT + 16 * lane;
    float b0[16];
    #pragma unroll
    for (int q = 0; q < 4; q++) {
      float4 t4 = *(const float4*)(wb + 4 * q);
      b0[4 * q] = t4.x; b0[4 * q + 1] = t4.y; b0[4 * q + 2] = t4.z; b0[4 * q + 3] = t4.w;
    }
    float b1[8], b2[4], b3[2], B4;
    #pragma unroll
    for (int j = 0; j < 8; j++) b1[j] = b0[2 * j] + b0[2 * j + 1];
    #pragma unroll
    for (int j = 0; j < 4; j++) b2[j] = b1[2 * j] + b1[2 * j + 1];
    #pragma unroll
    for (int j = 0; j < 2; j++) b3[j] = b2[2 * j] + b2[2 * j + 1];
    B4 = b3[0] + b3[1];
    float B5 = B4 + __shfl_down_sync(FULLW, B4, 1);
    float B6 = B5 + __shfl_down_sync(FULLW, B5, 2);
    float B7 = B6 + __shfl_down_sync(FULLW, B6, 4);
    float B8 = B7 + __shfl_down_sync(FULLW, B7, 8);
    float B9 = B8 + __shfl_down_sync(FULLW, B8, 16);
    float Sv = B9;
    #pragma unroll
    for (int lvl = 8; lvl >= 4; lvl--) {
      const int s = 1 << (lvl - 4);
      const float bl = (lvl == 8) ? B8 : (lvl == 7) ? B7 : (lvl == 6) ? B6
                     : (lvl == 5) ? B5 : B4;
      float up1 = __shfl_sync(FULLW, Sv, (lane >= s) ? lane - s : 0);
      float up2 = __shfl_sync(FULLW, Sv, (lane >= 2 * s) ? lane - 2 * s : 0);
      if ((lane & (s - 1)) == 0) {
        const int k = lane / s;
        Sv = (k == 0) ? bl : ((k & 1) ? up1 : up2 + bl);
      }
    }
    float P = __shfl_up_sync(FULLW, Sv, 1);
    const bool l0 = (lane == 0);
    float S3_0 = l0 ? b3[0] : P + b3[0];
    float S3_1 = Sv;
    float S2_0 = l0 ? b2[0] : P + b2[0];
    float S2_1 = S3_0;
    float S2_2 = S3_0 + b2[2];
    float S2_3 = S3_1;
    float S1[8];
    S1[0] = l0 ? b1[0] : P + b1[0];
    S1[1] = S2_0;
    S1[2] = S2_0 + b1[2];
    S1[3] = S2_1;
    S1[4] = S2_1 + b1[4];
    S1[5] = S2_2;
    S1[6] = S2_2 + b1[6];
    S1[7] = S2_3;
    float s[16];
    s[0] = l0 ? b0[0] : P + b0[0];
    #pragma unroll
    for (int m = 1; m < 16; m += 2) s[m] = S1[(m - 1) >> 1];
    #pragma unroll
    for (int m = 2; m < 16; m += 2) s[m] = S1[(m - 2) >> 1] + b0[m];
    float cv[16];
    #pragma unroll
    for (int m = 0; m < 16; m++) cv[m] = s[m] - 0.5f * b0[m];
    float* gc = g_c + b * TT + 16 * lane;
    #pragma unroll
    for (int q = 0; q < 4; q++) {
      float4 t4 = make_float4(cv[4 * q], cv[4 * q + 1], cv[4 * q + 2], cv[4 * q + 3]);
      *(float4*)(&c_sh[16 * lane + 4 * q]) = t4;
      *(float4*)(gc + 4 * q) = t4;
    }
  }
  __syncthreads();

  if (tid < NTILES) {
    const int t = tid;
    const float R = 14.0f;  // omitted/kept weight <= ~2e-6 (nearest kept <= 8)
    float tmin = (float)(t * TILE_F);
    float tmax = tmin + (float)(TILE_F - 1);
    int jlo = lower_bound_s(c_sh, tmin - R);
    int jhi = lower_bound_s(c_sh, tmax + R);
    int plo = lower_bound_s(c_sh, tmin);
    int phi = lower_bound_s(c_sh, tmax);
    jlo = min(jlo, max(plo - 1, 0));          // always include nearest tokens
    jhi = max(jhi, min(phi + 1, TT));
    jlo &= ~3;
    if (jhi - jlo > MAXBAND) {
      int slack = (max(0, (plo - 1) - jlo)) & ~3;
      int need  = jhi - jlo - MAXBAND;
      int adv   = min((need + 3) & ~3, slack);
      jlo += adv;
      jhi = min(jhi, jlo + MAXBAND);
    }
    g_band[b * NTILES + t] = make_int2(jlo, jhi);
  }

  // PDL: all writes above are visible to the dependent grid after its wait.
  asm volatile("griddepcontrol.launch_dependents;");
}

// ---------------------------------------------------------------------------
// Fused banded softmax + GEMM (R14 structure). Block = (32-frame tile, b),
// 256 threads, full 256 channels, thread tile 8ch x 4fr, 4 CTAs/SM.
// x_sT[c][tok]: row c = 32 tokens (128B); 16B unit u holds tokens 4u', with
// physical u = u' ^ ((c>>2)&7).
// ---------------------------------------------------------------------------
__global__ __launch_bounds__(NTHREADS, 4) void gauss_kernel(
    const float* __restrict__ x, float* __restrict__ out)
{
  __shared__ __align__(16) float x_sT[NC][MAXBAND];       // 32 KB, swizzled
  __shared__ __align__(16) float attn_s[MAXBAND][TILE_F]; // unnormalized E
  __shared__ float c_sh[MAXBAND];
  __shared__ float ps[8][TILE_F];
  __shared__ __align__(16) float r_s[TILE_F];

  const int b   = blockIdx.y;
  const int f0  = blockIdx.x * TILE_F;
  const int tid = threadIdx.x;

  // PDL: block until cumsum's writes (g_c, g_band) are visible.
  asm volatile("griddepcontrol.wait;" ::: "memory");

  const int2 bd = g_band[b * NTILES + blockIdx.x];
  const int jlo = bd.x;
  const int nband  = bd.y - jlo;
  const int nband4 = (nband + 3) & ~3;

  // ---- phase A: issue x loads (8 float4: 8 channels x 4 tokens) --------
  const int tq  = tid & 7;
  const int cl  = (tid >> 3) & 3;
  const int rep = tid >> 5;          // 0..7
  const int row0 = 4 * tq;
  const bool doload = row0 < nband4;
  float4 v[8];
  if (doload) {
    const bool full = (row0 + 4 <= nband);
    const float* xb = x + (size_t)b * NC * TT + jlo + row0;
    #pragma unroll
    for (int p = 0; p < 8; p++) {
      const int c = cl + 4 * rep + 32 * p;
      const float* src = xb + (size_t)c * TT;
      if (full) {
        v[p] = *(const float4*)src;
      } else {
        v[p].x = (row0     < nband) ? src[0] : 0.0f;
        v[p].y = (row0 + 1 < nband) ? src[1] : 0.0f;
        v[p].z = (row0 + 2 < nband) ? src[2] : 0.0f;
        v[p].w = (row0 + 3 < nband) ? src[3] : 0.0f;
      }
    }
  }

  if (tid < MAXBAND)
    c_sh[tid] = (tid < nband) ? g_c[b * TT + jlo + tid] : 3.0e38f;
  __syncthreads();                                   // #1: c_sh ready

  // ---- phase B: analytic softmax max + exp + partial sums; x STS -------
  const int fE   = tid & 31;
  const int kgrp = tid >> 5;
  {
    const float tf = (float)(f0 + fE);
    int lo = 0, hi = nband;          // nearest center (<=5 steps)
    while (lo < hi) { int mid = (lo + hi) >> 1; if (c_sh[mid] < tf) lo = mid + 1; else hi = mid; }
    float dR = (lo < nband) ? (c_sh[lo] - tf) : 3.0e38f;
    float dL = (lo > 0)     ? (tf - c_sh[lo - 1]) : 3.0e38f;
    float dmin = fminf(dL, dR);
    const float m = -DELTA_F * (dmin * dmin);        // exact band max

    float sloc = 0.0f;
    #pragma unroll
    for (int u = 0; u < 4; u++) {
      const int kk = kgrp + 8 * u;
      float E = 0.0f;
      if (kk < nband) {
        float d = tf - c_sh[kk];
        E = __expf(-DELTA_F * (d * d) - m);          // <= 1, NaN-safe
      }
      attn_s[kk][fE] = E;
      sloc += E;
    }
    ps[kgrp][fE] = sloc;
  }
  if (doload) {
    #pragma unroll
    for (int p = 0; p < 8; p++) {
      const int c = cl + 4 * rep + 32 * p;
      const int u = tq ^ rep;                        // = tq ^ ((c>>2)&7)
      *(float4*)&x_sT[c][4 * u] = v[p];
    }
  }
  __syncthreads();                                   // #2: attn_s, x_sT, ps ready
  if (tid < TILE_F) {
    float s = ps[0][tid];
    #pragma unroll
    for (int k = 1; k < 8; k++) s += ps[k][tid];
    r_s[tid] = 1.0f / s;
  }

  // ---- main FMA loop: 8ch x 4fr ---------------------------------------
  const int cg8 = tid >> 3;           // 0..31: channels 8*cg8 .. 8*cg8+7
  const int fg  = (tid & 7) << 2;     // frame base (4 frames)

  unsigned long long acc2[8][2];
  #pragma unroll
  for (int ci = 0; ci < 8; ci++) { acc2[ci][0] = 0ull; acc2[ci][1] = 0ull; }

  for (int kk0 = 0; kk0 < nband4; kk0 += 4) {
    #pragma unroll
    for (int h = 0; h < 2; h++) {                    // channel halves: regs <= 64
      const int key = (2 * cg8 + h) & 7;
      const int u4  = ((kk0 >> 2) ^ key) << 2;
      float4 xq[4];
      #pragma unroll
      for (int ci = 0; ci < 4; ci++)
        xq[ci] = *(const float4*)&x_sT[8 * cg8 + 4 * h + ci][u4];
      #pragma unroll
      for (int u = 0; u < 4; u++) {
        ulonglong2 ap = *(const ulonglong2*)&attn_s[kk0 + u][fg];
        const float xc[4] = {
          (u == 0) ? xq[0].x : (u == 1) ? xq[0].y : (u == 2) ? xq[0].z : xq[0].w,
          (u == 0) ? xq[1].x : (u == 1) ? xq[1].y : (u == 2) ? xq[1].z : xq[1].w,
          (u == 0) ? xq[2].x : (u == 1) ? xq[2].y : (u == 2) ? xq[2].z : xq[2].w,
          (u == 0) ? xq[3].x : (u == 1) ? xq[3].y : (u == 2) ? xq[3].z : xq[3].w };
        #pragma unroll
        for (int ci = 0; ci < 4; ci++) {
          unsigned long long xp;
          PACK2(xp, xc[ci], xc[ci]);
          FMA2(acc2[4 * h + ci][0], xp, ap.x);
          FMA2(acc2[4 * h + ci][1], xp, ap.y);
        }
      }
    }
  }
  __syncthreads();                                   // #3: r_s ready

  // ---- epilogue: normalize by r[f], store (4 rows/warp, full lines) ----
  ulonglong2 rp = *(const ulonglong2*)&r_s[fg];

  #pragma unroll
  for (int ci = 0; ci < 8; ci++) {
    unsigned long long t0, t1;
    MUL2(t0, acc2[ci][0], rp.x);
    MUL2(t1, acc2[ci][1], rp.y);
    float r0, r1, r2, r3;
    UNPACK2(r0, r1, t0);
    UNPACK2(r2, r3, t1);
    float* o = out + ((size_t)b * NC + 8 * cg8 + ci) * TFEAT + f0 + fg;
    *(float4*)o = make_float4(r0, r1, r2, r3);
  }
}

extern "C" void kernel_launch(void* const* d_in, const int* in_sizes, int n_in,
                              void* d_out, int out_size) {
  const float* x = (const float*)d_in[0];   // (B, C, T_text) fp32
  const float* w = (const float*)d_in[1];   // (B, T_text)    fp32
  float* out = (float*)d_out;               // (B, C, T_feat) fp32

  cumsum_kernel<<<NB, NTHREADS>>>(w);

  // gauss with programmatic dependent launch: overlaps its launch/setup with
  // the tail of cumsum; griddepcontrol.wait in-kernel enforces the data dep.
  cudaLaunchConfig_t cfg = {};
  cfg.gridDim  = dim3(NTILES, NB);
  cfg.blockDim = dim3(NTHREADS);
  cfg.dynamicSmemBytes = 0;
  cfg.stream = 0;
  cudaLaunchAttribute attr[1];
  attr[0].id = cudaLaunchAttributeProgrammaticStreamSerialization;
  attr[0].val.programmaticStreamSerializationAllowed = 1;
  cfg.attrs = attr;
  cfg.numAttrs = 1;
  cudaLaunchKernelEx(&cfg, gauss_kernel, x, out);
}

// round 16
// speedup vs baseline: 1.4212x; 1.0525x over previous
#include <cuda_runtime.h>

// GaussianUpsampling: out[b,c,f] = sum_j softmax_j(-0.1*(f - c_j)^2) * x[b,c,j]
//   c = cumsum(w) - 0.5*w   (bit-matches JAX associative_scan Brent-Kung tree)
// B=16, C=256, T_text=512, T_feat=4096. Masks structurally all-true.
//
// R16: occupancy via register diet. 8ch x 4fr thread tile processed as TWO
// sequential 4-channel passes (acc live 16 regs, not 32); x-STS issued first
// in phase B to release staging regs early; __launch_bounds__(256,5) ->
// 40 warps/SM. Band R=14 + PDL kept. cumsum = register Brent-Kung.

#define NB 16
#define NC 256
#define TT 512
#define TFEAT 4096
#define DELTA_F 0.1f
#define TILE_F 32
#define NTILES (TFEAT / TILE_F)   // 128
#define MAXBAND 32
#define NTHREADS 256
#define FULLW 0xffffffffu

__device__ float g_c[NB * TT];
__device__ int2  g_band[NB * NTILES];

#define FMA2(acc, a, b) \
  asm("fma.rn.f32x2 %0, %1, %2, %0;" : "+l"(acc) : "l"(a), "l"(b))
#define MUL2(out, a, b) \
  asm("mul.rn.f32x2 %0, %1, %2;" : "=l"(out) : "l"(a), "l"(b))
#define PACK2(out, lo, hi) \
  asm("mov.b64 %0, {%1, %2};" : "=l"(out) : "f"(lo), "f"(hi))
#define UNPACK2(lo, hi, in) \
  asm("mov.b64 {%0, %1}, %2;" : "=f"(lo), "=f"(hi) : "l"(in))

__device__ __forceinline__ int lower_bound_s(const float* c, float v) {
  int lo = 0, hi = TT;
  while (lo < hi) { int m = (lo + hi) >> 1; if (c[m] < v) lo = m + 1; else hi = m; }
  return lo;
}

// ---------------------------------------------------------------------------
// Register Brent-Kung scan (warp 0) + parallel band computation.
// ---------------------------------------------------------------------------
__global__ void cumsum_kernel(const float* __restrict__ w) {
  __shared__ float c_sh[TT];
  const int b   = blockIdx.x;
  const int tid = threadIdx.x;

  if (tid < 32) {
    const int lane = tid;
    const float* wb = w + b * TT + 16 * lane;
    float b0[16];
    #pragma unroll
    for (int q = 0; q < 4; q++) {
      float4 t4 = *(const float4*)(wb + 4 * q);
      b0[4 * q] = t4.x; b0[4 * q + 1] = t4.y; b0[4 * q + 2] = t4.z; b0[4 * q + 3] = t4.w;
    }
    float b1[8], b2[4], b3[2], B4;
    #pragma unroll
    for (int j = 0; j < 8; j++) b1[j] = b0[2 * j] + b0[2 * j + 1];
    #pragma unroll
    for (int j = 0; j < 4; j++) b2[j] = b1[2 * j] + b1[2 * j + 1];
    #pragma unroll
    for (int j = 0; j < 2; j++) b3[j] = b2[2 * j] + b2[2 * j + 1];
    B4 = b3[0] + b3[1];
    float B5 = B4 + __shfl_down_sync(FULLW, B4, 1);
    float B6 = B5 + __shfl_down_sync(FULLW, B5, 2);
    float B7 = B6 + __shfl_down_sync(FULLW, B6, 4);
    float B8 = B7 + __shfl_down_sync(FULLW, B7, 8);
    float B9 = B8 + __shfl_down_sync(FULLW, B8, 16);
    float Sv = B9;
    #pragma unroll
    for (int lvl = 8; lvl >= 4; lvl--) {
      const int s = 1 << (lvl - 4);
      const float bl = (lvl == 8) ? B8 : (lvl == 7) ? B7 : (lvl == 6) ? B6
                     : (lvl == 5) ? B5 : B4;
      float up1 = __shfl_sync(FULLW, Sv, (lane >= s) ? lane - s : 0);
      float up2 = __shfl_sync(FULLW, Sv, (lane >= 2 * s) ? lane - 2 * s : 0);
      if ((lane & (s - 1)) == 0) {
        const int k = lane / s;
        Sv = (k == 0) ? bl : ((k & 1) ? up1 : up2 + bl);
      }
    }
    float P = __shfl_up_sync(FULLW, Sv, 1);
    const bool l0 = (lane == 0);
    float S3_0 = l0 ? b3[0] : P + b3[0];
    float S3_1 = Sv;
    float S2_0 = l0 ? b2[0] : P + b2[0];
    float S2_1 = S3_0;
    float S2_2 = S3_0 + b2[2];
    float S2_3 = S3_1;
    float S1[8];
    S1[0] = l0 ? b1[0] : P + b1[0];
    S1[1] = S2_0;
    S1[2] = S2_0 + b1[2];
    S1[3] = S2_1;
    S1[4] = S2_1 + b1[4];
    S1[5] = S2_2;
    S1[6] = S2_2 + b1[6];
    S1[7] = S2_3;
    float s[16];
    s[0] = l0 ? b0[0] : P + b0[0];
    #pragma unroll
    for (int m = 1; m < 16; m += 2) s[m] = S1[(m - 1) >> 1];
    #pragma unroll
    for (int m = 2; m < 16; m += 2) s[m] = S1[(m - 2) >> 1] + b0[m];
    float cv[16];
    #pragma unroll
    for (int m = 0; m < 16; m++) cv[m] = s[m] - 0.5f * b0[m];
    float* gc = g_c + b * TT + 16 * lane;
    #pragma unroll
    for (int q = 0; q < 4; q++) {
      float4 t4 = make_float4(cv[4 * q], cv[4 * q + 1], cv[4 * q + 2], cv[4 * q + 3]);
      *(float4*)(&c_sh[16 * lane + 4 * q]) = t4;
      *(float4*)(gc + 4 * q) = t4;
    }
  }
  __syncthreads();

  if (tid < NTILES) {
    const int t = tid;
    const float R = 14.0f;  // omitted/kept weight <= ~2e-6 (nearest kept <= 8)
    float tmin = (float)(t * TILE_F);
    float tmax = tmin + (float)(TILE_F - 1);
    int jlo = lower_bound_s(c_sh, tmin - R);
    int jhi = lower_bound_s(c_sh, tmax + R);
    int plo = lower_bound_s(c_sh, tmin);
    int phi = lower_bound_s(c_sh, tmax);
    jlo = min(jlo, max(plo - 1, 0));          // always include nearest tokens
    jhi = max(jhi, min(phi + 1, TT));
    jlo &= ~3;
    if (jhi - jlo > MAXBAND) {
      int slack = (max(0, (plo - 1) - jlo)) & ~3;
      int need  = jhi - jlo - MAXBAND;
      int adv   = min((need + 3) & ~3, slack);
      jlo += adv;
      jhi = min(jhi, jlo + MAXBAND);
    }
    g_band[b * NTILES + t] = make_int2(jlo, jhi);
  }

  asm volatile("griddepcontrol.launch_dependents;");
}

// ---------------------------------------------------------------------------
// Fused banded softmax + GEMM. Block = (32-frame tile, batch), 256 threads,
// full 256 channels. Thread tile 8ch x 4fr in TWO 4-channel passes.
// __launch_bounds__(256,5): 40 warps/SM.
// x_sT[c][tok]: row c = 32 tokens (128B); unit u = u' ^ ((c>>2)&7).
// ---------------------------------------------------------------------------
__global__ __launch_bounds__(NTHREADS, 5) void gauss_kernel(
    const float* __restrict__ x, float* __restrict__ out)
{
  __shared__ __align__(16) float x_sT[NC][MAXBAND];       // 32 KB, swizzled
  __shared__ __align__(16) float attn_s[MAXBAND][TILE_F]; // unnormalized E
  __shared__ float c_sh[MAXBAND];
  __shared__ float ps[8][TILE_F];
  __shared__ __align__(16) float r_s[TILE_F];

  const int b   = blockIdx.y;
  const int f0  = blockIdx.x * TILE_F;
  const int tid = threadIdx.x;

  asm volatile("griddepcontrol.wait;" ::: "memory");

  const int2 bd = g_band[b * NTILES + blockIdx.x];
  const int jlo = bd.x;
  const int nband  = bd.y - jlo;
  const int nband4 = (nband + 3) & ~3;

  // ---- phase A: issue x loads (8 float4: 8 channels x 4 tokens) --------
  const int tq  = tid & 7;
  const int cl  = (tid >> 3) & 3;
  const int rep = tid >> 5;          // 0..7
  const int row0 = 4 * tq;
  const bool doload = row0 < nband4;
  {
    float4 v[8];
    if (doload) {
      const bool full = (row0 + 4 <= nband);
      const float* xb = x + (size_t)b * NC * TT + jlo + row0;
      #pragma unroll
      for (int p = 0; p < 8; p++) {
        const int c = cl + 4 * rep + 32 * p;
        const float* src = xb + (size_t)c * TT;
        if (full) {
          v[p] = *(const float4*)src;
        } else {
          v[p].x = (row0     < nband) ? src[0] : 0.0f;
          v[p].y = (row0 + 1 < nband) ? src[1] : 0.0f;
          v[p].z = (row0 + 2 < nband) ? src[2] : 0.0f;
          v[p].w = (row0 + 3 < nband) ? src[3] : 0.0f;
        }
      }
    }

    if (tid < MAXBAND)
      c_sh[tid] = (tid < nband) ? g_c[b * TT + jlo + tid] : 3.0e38f;
    __syncthreads();                                 // #1: c_sh ready

    // STS first: releases the v[] staging registers before the exp work.
    if (doload) {
      #pragma unroll
      for (int p = 0; p < 8; p++) {
        const int c = cl + 4 * rep + 32 * p;
        const int u = tq ^ rep;                      // = tq ^ ((c>>2)&7)
        *(float4*)&x_sT[c][4 * u] = v[p];
      }
    }
  }

  // ---- phase B: analytic softmax max + exp + partial sums --------------
  const int fE   = tid & 31;
  const int kgrp = tid >> 5;
  {
    const float tf = (float)(f0 + fE);
    int lo = 0, hi = nband;          // nearest center (<=5 steps)
    while (lo < hi) { int mid = (lo + hi) >> 1; if (c_sh[mid] < tf) lo = mid + 1; else hi = mid; }
    float dR = (lo < nband) ? (c_sh[lo] - tf) : 3.0e38f;
    float dL = (lo > 0)     ? (tf - c_sh[lo - 1]) : 3.0e38f;
    float dmin = fminf(dL, dR);
    const float m = -DELTA_F * (dmin * dmin);        // exact band max

    float sloc = 0.0f;
    #pragma unroll
    for (int u = 0; u < 4; u++) {
      const int kk = kgrp + 8 * u;
      float E = 0.0f;
      if (kk < nband) {
        float d = tf - c_sh[kk];
        E = __expf(-DELTA_F * (d * d) - m);          // <= 1, NaN-safe
      }
      attn_s[kk][fE] = E;
      sloc += E;
    }
    ps[kgrp][fE] = sloc;
  }
  __syncthreads();                                   // #2: attn_s, x_sT, ps ready
  if (tid < TILE_F) {
    float s = ps[0][tid];
    #pragma unroll
    for (int k = 1; k < 8; k++) s += ps[k][tid];
    r_s[tid] = 1.0f / s;
  }

  // ---- main loop: two 4-channel passes ---------------------------------
  const int cg8 = tid >> 3;           // 0..31: channels 8*cg8 .. 8*cg8+7
  const int fg  = (tid & 7) << 2;     // frame base (4 frames)

  #pragma unroll
  for (int h = 0; h < 2; h++) {
    unsigned long long acc2[4][2];
    #pragma unroll
    for (int ci = 0; ci < 4; ci++) { acc2[ci][0] = 0ull; acc2[ci][1] = 0ull; }

    const int key = (2 * cg8 + h) & 7;
    for (int kk0 = 0; kk0 < nband4; kk0 += 4) {
      const int u4 = ((kk0 >> 2) ^ key) << 2;
      float4 xq[4];                                  // 4 channels x 4 tokens
      #pragma unroll
      for (int ci = 0; ci < 4; ci++)
        xq[ci] = *(const float4*)&x_sT[8 * cg8 + 4 * h + ci][u4];
      #pragma unroll
      for (int u = 0; u < 4; u++) {
        ulonglong2 ap = *(const ulonglong2*)&attn_s[kk0 + u][fg];
        const float xc[4] = {
          (u == 0) ? xq[0].x : (u == 1) ? xq[0].y : (u == 2) ? xq[0].z : xq[0].w,
          (u == 0) ? xq[1].x : (u == 1) ? xq[1].y : (u == 2) ? xq[1].z : xq[1].w,
          (u == 0) ? xq[2].x : (u == 1) ? xq[2].y : (u == 2) ? xq[2].z : xq[2].w,
          (u == 0) ? xq[3].x : (u == 1) ? xq[3].y : (u == 2) ? xq[3].z : xq[3].w };
        #pragma unroll
        for (int ci = 0; ci < 4; ci++) {
          unsigned long long xp;
          PACK2(xp, xc[ci], xc[ci]);
          FMA2(acc2[ci][0], xp, ap.x);
          FMA2(acc2[ci][1], xp, ap.y);
        }
      }
    }

    if (h == 0) __syncthreads();                     // #3: r_s ready (once)

    ulonglong2 rp = *(const ulonglong2*)&r_s[fg];
    #pragma unroll
    for (int ci = 0; ci < 4; ci++) {
      unsigned long long t0, t1;
      MUL2(t0, acc2[ci][0], rp.x);
      MUL2(t1, acc2[ci][1], rp.y);
      float r0, r1, r2, r3;
      UNPACK2(r0, r1, t0);
      UNPACK2(r2, r3, t1);
      float* o = out + ((size_t)b * NC + 8 * cg8 + 4 * h + ci) * TFEAT + f0 + fg;
      *(float4*)o = make_float4(r0, r1, r2, r3);
    }
  }
}

extern "C" void kernel_launch(void* const* d_in, const int* in_sizes, int n_in,
                              void* d_out, int out_size) {
  const float* x = (const float*)d_in[0];   // (B, C, T_text) fp32
  const float* w = (const float*)d_in[1];   // (B, T_text)    fp32
  float* out = (float*)d_out;               // (B, C, T_feat) fp32

  cumsum_kernel<<<NB, NTHREADS>>>(w);

  cudaLaunchConfig_t cfg = {};
  cfg.gridDim  = dim3(NTILES, NB);
  cfg.blockDim = dim3(NTHREADS);
  cfg.dynamicSmemBytes = 0;
  cfg.stream = 0;
  cudaLaunchAttribute attr[1];
  attr[0].id = cudaLaunchAttributeProgrammaticStreamSerialization;
  attr[0].val.programmaticStreamSerializationAllowed = 1;
  cfg.attrs = attr;
  cfg.numAttrs = 1;
  cudaLaunchKernelEx(&cfg, gauss_kernel, x, out);
}